// round 7
// baseline (speedup 1.0000x reference)
#include <cuda_runtime.h>

// IF spiking neuron forward (R7 = R6 core + persistent one-wave grid):
//   x: [T=8, N=4194304] fp32, thresh: [1] fp32
//   mem = 0.5*thr; per t: m = mem + x[t]; s = (m>=thr); out[t] = s*thr; mem = m - s*thr
//
// R6 measured: 36.2us device, DRAM 74.7% (5.91 TB/s) at 4096 CTAs (3.46 waves
// of 1184 concurrent). R7 launches exactly one wave (1184 CTAs, 8/SM) with a
// grid-stride loop to remove the fractional-wave tail. Reg budget forced to 32
// (2048 thr/SM x 32 regs = full 64K regfile) via __launch_bounds__(256, 8).

#define T_STEPS 8
#define N_NEURONS (256 / T_STEPS * 512 * 16 * 16)   // 4,194,304
#define N4 (N_NEURONS / 4)                           // 1,048,576 float4 per timestep
#define TPB 256
#define NUM_SMS 148
#define CTAS_PER_SM 8
#define GRID (NUM_SMS * CTAS_PER_SM)                 // 1184 = one full wave

__global__ __launch_bounds__(TPB, CTAS_PER_SM) void if_forward_kernel(
    const float4* __restrict__ x,
    const float* __restrict__ thresh,
    float4* __restrict__ out)
{
    const float thr = __ldg(thresh);
    const int stride = GRID * TPB;  // compile-time constant stride

    for (int i = blockIdx.x * TPB + threadIdx.x; i < N4; i += stride) {
        // Front-batch the 8 timestep loads for this chunk.
        float4 xv[T_STEPS];
#pragma unroll
        for (int t = 0; t < T_STEPS; t++) {
            xv[t] = x[(size_t)t * N4 + i];
        }

        float m0 = 0.5f * thr, m1 = m0, m2 = m0, m3 = m0;

#pragma unroll
        for (int t = 0; t < T_STEPS; t++) {
            m0 += xv[t].x;
            m1 += xv[t].y;
            m2 += xv[t].z;
            m3 += xv[t].w;
            float4 sp;
            sp.x = (m0 >= thr) ? thr : 0.0f;
            sp.y = (m1 >= thr) ? thr : 0.0f;
            sp.z = (m2 >= thr) ? thr : 0.0f;
            sp.w = (m3 >= thr) ? thr : 0.0f;
            m0 -= sp.x;
            m1 -= sp.y;
            m2 -= sp.z;
            m3 -= sp.w;
            out[(size_t)t * N4 + i] = sp;
        }
    }
}

extern "C" void kernel_launch(void* const* d_in, const int* in_sizes, int n_in,
                              void* d_out, int out_size) {
    const float4* x = (const float4*)d_in[0];
    const float* thresh = (const float*)d_in[1];
    float4* out = (float4*)d_out;

    if_forward_kernel<<<GRID, TPB>>>(x, thresh, out);
}

// round 8
// speedup vs baseline: 1.0816x; 1.0816x over previous
#include <cuda_runtime.h>

// IF spiking neuron forward (R8 = R6 core, TPB=128 for finer CTA granularity):
//   x: [T=8, N=4194304] fp32, thresh: [1] fp32
//   mem = 0.5*thr; per t: m = mem + x[t]; s = (m>=thr); out[t] = s*thr; mem = m - s*thr
//
// Evidence so far (device time / DRAM%):
//   R6 4096x256 plain:        36.2us / 74.7%   <- best
//   R4 2048x512 +hints:       37.1us / 72.9%
//   R3 ITEMS=2 +hints:        38.3us / 70.6%
//   R7 persistent 1184 CTAs:  39.0us / 69.9%   (burst-drain phasing hurts)
//   R5 R2+hints:              43.1us / 69.8%   (streaming hints actively harm)
// R8 halves CTA size: 8192 CTAs, 16/SM resident, same 32-reg/occ picture,
// finer work-steal tail + smoother load-burst interleave across CTA streams.

#define T_STEPS 8
#define N_NEURONS (256 / T_STEPS * 512 * 16 * 16)   // 4,194,304
#define N4 (N_NEURONS / 4)                           // 1,048,576 float4 per timestep
#define TPB 128

__global__ __launch_bounds__(TPB) void if_forward_kernel(
    const float4* __restrict__ x,
    const float* __restrict__ thresh,
    float4* __restrict__ out)
{
    const int i = blockIdx.x * TPB + threadIdx.x;  // grid exactly covers N4
    const float thr = __ldg(thresh);

    // Front-batch the 8 timestep loads (MLP = 8 x LDG.128 per thread).
    float4 xv[T_STEPS];
#pragma unroll
    for (int t = 0; t < T_STEPS; t++) {
        xv[t] = x[(size_t)t * N4 + i];
    }

    float m0 = 0.5f * thr, m1 = m0, m2 = m0, m3 = m0;

#pragma unroll
    for (int t = 0; t < T_STEPS; t++) {
        m0 += xv[t].x;
        m1 += xv[t].y;
        m2 += xv[t].z;
        m3 += xv[t].w;
        float4 sp;
        sp.x = (m0 >= thr) ? thr : 0.0f;
        sp.y = (m1 >= thr) ? thr : 0.0f;
        sp.z = (m2 >= thr) ? thr : 0.0f;
        sp.w = (m3 >= thr) ? thr : 0.0f;
        m0 -= sp.x;
        m1 -= sp.y;
        m2 -= sp.z;
        m3 -= sp.w;
        out[(size_t)t * N4 + i] = sp;
    }
}

extern "C" void kernel_launch(void* const* d_in, const int* in_sizes, int n_in,
                              void* d_out, int out_size) {
    const float4* x = (const float4*)d_in[0];
    const float* thresh = (const float*)d_in[1];
    float4* out = (float4*)d_out;

    const int blocks = N4 / TPB;  // 8192, exact
    if_forward_kernel<<<blocks, TPB>>>(x, thresh, out);
}

// round 10
// speedup vs baseline: 1.0933x; 1.0108x over previous
#include <cuda_runtime.h>

// IF spiking neuron forward (R10 = R9 resubmit; prior round was an infra
// failure — "GB300 container failed twice" — not a kernel failure):
//   x: [T=8, N=4194304] fp32, thresh: [1] fp32
//   mem = 0.5*thr; per t: m = mem + x[t]; s = (m>=thr); out[t] = s*thr; mem = m - s*thr
//
// Evidence (device time / DRAM%):
//   R6 4096x256 plain:        36.2us / 74.7%   <- best
//   R8 8192x128 plain:        36.4us / 74.4%   (CTA size neutral)
//   R4 2048x512 +ldcs:        37.1us / 72.9%
//   R3 ITEMS=2:               38.3us / 70.6%
//   R7 persistent 1184:       39.0us / 69.9%
//   R5 R6+ldcs/stcs:          43.1us / 69.8%   (.cs L2 evict-first policy harms)
// This round isolates .cg: bypass L1 (zero reuse -> L1 fill is pure overhead)
// while keeping DEFAULT L2 policy (which R5 proved is load-bearing). Stores
// unchanged. Final A/B; on neutral or regression the R6 config is the
// converged roofline answer (~74% of 8TB/s on a 1:1 R/W stream).

#define T_STEPS 8
#define N_NEURONS (256 / T_STEPS * 512 * 16 * 16)   // 4,194,304
#define N4 (N_NEURONS / 4)                           // 1,048,576 float4 per timestep
#define TPB 256

__global__ __launch_bounds__(TPB) void if_forward_kernel(
    const float4* __restrict__ x,
    const float* __restrict__ thresh,
    float4* __restrict__ out)
{
    const int i = blockIdx.x * TPB + threadIdx.x;  // grid exactly covers N4
    const float thr = __ldg(thresh);

    // Front-batch the 8 timestep loads; .cg = cache at L2 only (skip L1 fill,
    // keep default L2 replacement policy).
    float4 xv[T_STEPS];
#pragma unroll
    for (int t = 0; t < T_STEPS; t++) {
        xv[t] = __ldcg(&x[(size_t)t * N4 + i]);
    }

    float m0 = 0.5f * thr, m1 = m0, m2 = m0, m3 = m0;

#pragma unroll
    for (int t = 0; t < T_STEPS; t++) {
        m0 += xv[t].x;
        m1 += xv[t].y;
        m2 += xv[t].z;
        m3 += xv[t].w;
        float4 sp;
        sp.x = (m0 >= thr) ? thr : 0.0f;
        sp.y = (m1 >= thr) ? thr : 0.0f;
        sp.z = (m2 >= thr) ? thr : 0.0f;
        sp.w = (m3 >= thr) ? thr : 0.0f;
        m0 -= sp.x;
        m1 -= sp.y;
        m2 -= sp.z;
        m3 -= sp.w;
        out[(size_t)t * N4 + i] = sp;
    }
}

extern "C" void kernel_launch(void* const* d_in, const int* in_sizes, int n_in,
                              void* d_out, int out_size) {
    const float4* x = (const float4*)d_in[0];
    const float* thresh = (const float*)d_in[1];
    float4* out = (float4*)d_out;

    const int blocks = N4 / TPB;  // 4096, exact
    if_forward_kernel<<<blocks, TPB>>>(x, thresh, out);
}